// round 3
// baseline (speedup 1.0000x reference)
#include <cuda_runtime.h>

// Problem shapes (fixed for this benchmark instance)
#define M_TOK 4096   // B*S = 2*2048
#define HDIM  2048   // H (input dim / K of base GEMM)
#define ODIM  2048   // O (output dim / N)
#define NEXP  8      // experts
#define RANK  16     // LoRA rank
#define ER    128    // NEXP * RANK
#define ALPHA 16.0f  // LORA_ALPHA

// Scratch (no cudaMalloc allowed): per-token combine weights and LoRA-down result
__device__ float g_cw[M_TOK * NEXP];   // 128 KB
__device__ float g_t[M_TOK * ER];      // 2 MB

// ---------------------------------------------------------------------------
// Kernel 1: router. One CTA per token: logits = x[m] @ gate_w^T, softmax,
// top-2, renormalize -> g_cw[m][e] (zero except the two selected experts).
// ---------------------------------------------------------------------------
__global__ __launch_bounds__(256)
void router_kernel(const float* __restrict__ x, const float* __restrict__ gw) {
    int m = blockIdx.x;
    int tid = threadIdx.x;
    const float* xr = x + (size_t)m * HDIM;

    float acc[NEXP];
#pragma unroll
    for (int e = 0; e < NEXP; e++) acc[e] = 0.f;

    for (int k = tid; k < HDIM; k += 256) {
        float xv = xr[k];
#pragma unroll
        for (int e = 0; e < NEXP; e++) acc[e] = fmaf(xv, gw[e * HDIM + k], acc[e]);
    }

    // warp reduce
#pragma unroll
    for (int off = 16; off; off >>= 1) {
#pragma unroll
        for (int e = 0; e < NEXP; e++)
            acc[e] += __shfl_down_sync(0xffffffffu, acc[e], off);
    }

    __shared__ float red[8][NEXP];
    int wid = tid >> 5, lane = tid & 31;
    if (lane == 0) {
#pragma unroll
        for (int e = 0; e < NEXP; e++) red[wid][e] = acc[e];
    }
    __syncthreads();

    if (tid == 0) {
        float lg[NEXP];
#pragma unroll
        for (int e = 0; e < NEXP; e++) {
            float s = 0.f;
#pragma unroll
            for (int w = 0; w < 8; w++) s += red[w][e];
            lg[e] = s;
        }
        float mx = lg[0];
#pragma unroll
        for (int e = 1; e < NEXP; e++) mx = fmaxf(mx, lg[e]);
        float ex[NEXP];
#pragma unroll
        for (int e = 0; e < NEXP; e++) ex[e] = expf(lg[e] - mx);
        // top-2 (ties -> lowest index, matching jax top_k)
        int i1 = 0;
#pragma unroll
        for (int e = 1; e < NEXP; e++) if (ex[e] > ex[i1]) i1 = e;
        int i2 = (i1 == 0) ? 1 : 0;
#pragma unroll
        for (int e = 0; e < NEXP; e++) {
            if (e == i1) continue;
            if (ex[e] > ex[i2]) i2 = e;
        }
        // softmax normalization cancels under top-2 renormalization
        float s2 = ex[i1] + ex[i2];
        float* cwm = g_cw + (size_t)m * NEXP;
#pragma unroll
        for (int e = 0; e < NEXP; e++) cwm[e] = 0.f;
        cwm[i1] = ex[i1] / s2;
        cwm[i2] = ex[i2] / s2;
    }
}

// ---------------------------------------------------------------------------
// Kernel 2: LoRA down-projection GEMM. t[M_TOK, ER] = x[M_TOK, HDIM] @ A^T,
// with A_w flattened to [ER, HDIM]. Tiles: BM=64, BN=64, BK=16, 256 thr, 4x4.
// ---------------------------------------------------------------------------
__global__ __launch_bounds__(256)
void loraA_kernel(const float* __restrict__ x, const float* __restrict__ Aw) {
    __shared__ float As[16][64];
    __shared__ float Bs[16][64];

    int n0 = blockIdx.x * 64;
    int m0 = blockIdx.y * 64;
    int tid = threadIdx.x;
    int tx = tid & 15;   // 16 col groups * 4
    int ty = tid >> 4;   // 16 row groups * 4

    float acc[4][4];
#pragma unroll
    for (int i = 0; i < 4; i++)
#pragma unroll
        for (int j = 0; j < 4; j++) acc[i][j] = 0.f;

    int row = tid >> 2;
    int c4 = (tid & 3) * 4;

    for (int k0 = 0; k0 < HDIM; k0 += 16) {
        float4 va = *(const float4*)(x + (size_t)(m0 + row) * HDIM + k0 + c4);
        As[c4 + 0][row] = va.x; As[c4 + 1][row] = va.y;
        As[c4 + 2][row] = va.z; As[c4 + 3][row] = va.w;
        float4 vb = *(const float4*)(Aw + (size_t)(n0 + row) * HDIM + k0 + c4);
        Bs[c4 + 0][row] = vb.x; Bs[c4 + 1][row] = vb.y;
        Bs[c4 + 2][row] = vb.z; Bs[c4 + 3][row] = vb.w;
        __syncthreads();

#pragma unroll
        for (int kk = 0; kk < 16; kk++) {
            float a[4], b[4];
            *(float4*)a = *(const float4*)&As[kk][ty * 4];
            *(float4*)b = *(const float4*)&Bs[kk][tx * 4];
#pragma unroll
            for (int i = 0; i < 4; i++)
#pragma unroll
                for (int j = 0; j < 4; j++)
                    acc[i][j] = fmaf(a[i], b[j], acc[i][j]);
        }
        __syncthreads();
    }

#pragma unroll
    for (int i = 0; i < 4; i++) {
        float4 v = make_float4(acc[i][0], acc[i][1], acc[i][2], acc[i][3]);
        *(float4*)(g_t + (size_t)(m0 + ty * 4 + i) * ER + n0 + tx * 4) = v;
    }
}

// ---------------------------------------------------------------------------
// Kernel 3: fused main GEMM. out[m,o] = sum_k x[m,k]*W[o,k]
//                                     + sum_j (alpha*cw[m,e]*t[m,j]) * B_w[e,o,r]
// where j = e*16+r. The LoRA part is 8 extra K-tiles of width 16 (one per
// expert; B_w[e,o,:] is contiguous -> coalesced float4 loads).
// Tiles: BM=BN=128, BK=16, 256 threads, 8x8 microtile.
// ---------------------------------------------------------------------------
__global__ __launch_bounds__(256, 2)
void main_gemm(const float* __restrict__ x, const float* __restrict__ w,
               const float* __restrict__ Bw, float* __restrict__ out) {
    __shared__ float As[16][128];
    __shared__ float Bs[16][128];

    int n0 = blockIdx.x * 128;
    int m0 = blockIdx.y * 128;
    int tid = threadIdx.x;
    int tx = tid & 15;   // 16 * 8 cols
    int ty = tid >> 4;   // 16 * 8 rows

    float acc[8][8];
#pragma unroll
    for (int i = 0; i < 8; i++)
#pragma unroll
        for (int j = 0; j < 8; j++) acc[i][j] = 0.f;

    // ---- main K loop over HDIM ----
    for (int k0 = 0; k0 < HDIM; k0 += 16) {
#pragma unroll
        for (int i = 0; i < 2; i++) {
            int pos = tid + i * 256;
            int row = pos >> 2;
            int c4 = (pos & 3) * 4;
            float4 va = *(const float4*)(x + (size_t)(m0 + row) * HDIM + k0 + c4);
            As[c4 + 0][row] = va.x; As[c4 + 1][row] = va.y;
            As[c4 + 2][row] = va.z; As[c4 + 3][row] = va.w;
            float4 vb = *(const float4*)(w + (size_t)(n0 + row) * HDIM + k0 + c4);
            Bs[c4 + 0][row] = vb.x; Bs[c4 + 1][row] = vb.y;
            Bs[c4 + 2][row] = vb.z; Bs[c4 + 3][row] = vb.w;
        }
        __syncthreads();

#pragma unroll
        for (int kk = 0; kk < 16; kk++) {
            float a[8], b[8];
#pragma unroll
            for (int i = 0; i < 8; i += 4)
                *(float4*)&a[i] = *(const float4*)&As[kk][ty * 8 + i];
#pragma unroll
            for (int j = 0; j < 8; j += 4)
                *(float4*)&b[j] = *(const float4*)&Bs[kk][tx * 8 + j];
#pragma unroll
            for (int i = 0; i < 8; i++)
#pragma unroll
                for (int j = 0; j < 8; j++)
                    acc[i][j] = fmaf(a[i], b[j], acc[i][j]);
        }
        __syncthreads();
    }

    // ---- LoRA extra-K loop: 8 tiles of 16 (one expert each) ----
    for (int e = 0; e < NEXP; e++) {
#pragma unroll
        for (int i = 0; i < 2; i++) {
            int pos = tid + i * 256;
            int row = pos >> 2;
            int c4 = (pos & 3) * 4;
            float scale = ALPHA * g_cw[(size_t)(m0 + row) * NEXP + e];
            float4 va = *(const float4*)(g_t + (size_t)(m0 + row) * ER + e * RANK + c4);
            As[c4 + 0][row] = va.x * scale; As[c4 + 1][row] = va.y * scale;
            As[c4 + 2][row] = va.z * scale; As[c4 + 3][row] = va.w * scale;
            // B_w[e, o, r]: contiguous in r (RANK=16 = 4 float4s)
            float4 vb = *(const float4*)(Bw + ((size_t)e * ODIM + n0 + row) * RANK + c4);
            Bs[c4 + 0][row] = vb.x; Bs[c4 + 1][row] = vb.y;
            Bs[c4 + 2][row] = vb.z; Bs[c4 + 3][row] = vb.w;
        }
        __syncthreads();

#pragma unroll
        for (int kk = 0; kk < 16; kk++) {
            float a[8], b[8];
#pragma unroll
            for (int i = 0; i < 8; i += 4)
                *(float4*)&a[i] = *(const float4*)&As[kk][ty * 8 + i];
#pragma unroll
            for (int j = 0; j < 8; j += 4)
                *(float4*)&b[j] = *(const float4*)&Bs[kk][tx * 8 + j];
#pragma unroll
            for (int i = 0; i < 8; i++)
#pragma unroll
                for (int j = 0; j < 8; j++)
                    acc[i][j] = fmaf(a[i], b[j], acc[i][j]);
        }
        __syncthreads();
    }

    // ---- epilogue ----
#pragma unroll
    for (int i = 0; i < 8; i++) {
        float* orow = out + (size_t)(m0 + ty * 8 + i) * ODIM + n0 + tx * 8;
        *(float4*)orow = make_float4(acc[i][0], acc[i][1], acc[i][2], acc[i][3]);
        *(float4*)(orow + 4) = make_float4(acc[i][4], acc[i][5], acc[i][6], acc[i][7]);
    }
}

// ---------------------------------------------------------------------------
extern "C" void kernel_launch(void* const* d_in, const int* in_sizes, int n_in,
                              void* d_out, int out_size) {
    const float* x  = (const float*)d_in[0];   // [2,2048,2048]
    const float* w  = (const float*)d_in[1];   // [2048,2048]
    const float* gw = (const float*)d_in[2];   // [8,2048]
    const float* Aw = (const float*)d_in[3];   // [8,16,2048] -> [128,2048]
    const float* Bw = (const float*)d_in[4];   // [8,2048,16]
    float* out = (float*)d_out;                // [2,2048,2048]

    router_kernel<<<M_TOK, 256>>>(x, gw);

    dim3 gA(ER / 64, M_TOK / 64);              // (2, 64)
    loraA_kernel<<<gA, 256>>>(x, Aw);

    dim3 gM(ODIM / 128, M_TOK / 128);          // (16, 32)
    main_gemm<<<gM, 256>>>(x, w, Bw, out);
}

// round 7
// speedup vs baseline: 2.5508x; 2.5508x over previous
#include <cuda_runtime.h>
#include <cstdint>

// Problem shapes (fixed for this benchmark instance)
#define M_TOK 4096   // B*S
#define HDIM  2048   // H
#define ODIM  2048   // O
#define NEXP  8
#define RANK  16
#define ER    128    // NEXP*RANK
#define ALPHA 16.0f

// Scratch (no cudaMalloc allowed)
__device__ float g_cw[M_TOK * NEXP];   // 128 KB combine weights
__device__ float g_t[M_TOK * ER];      // 2 MB LoRA-down result

// ===========================================================================
// PTX helpers — ONLY compute_103-legal features (sm_80-era PTX).
// ===========================================================================
__device__ __forceinline__ uint32_t smem_u32(const void* p) {
    uint32_t a;
    asm("{ .reg .u64 t; cvta.to.shared.u64 t, %1; cvt.u32.u64 %0, t; }"
        : "=r"(a) : "l"(p));
    return a;
}

__device__ __forceinline__ uint32_t f2tf32(float x) {
    uint32_t r;
    asm("cvt.rna.tf32.f32 %0, %1;" : "=r"(r) : "f"(x));
    return r;
}

#define CP_ASYNC16(dst_u32, src_ptr) \
    asm volatile("cp.async.cg.shared.global [%0], [%1], 16;" \
                 :: "r"(dst_u32), "l"(src_ptr) : "memory")
#define CP_COMMIT() asm volatile("cp.async.commit_group;" ::: "memory")
#define CP_WAIT(n)  asm volatile("cp.async.wait_group %0;" :: "n"(n) : "memory")

// D += A*B, tf32 m16n8k8 (row.col), fp32 accumulate
__device__ __forceinline__ void mma_tf32(float* d, const uint32_t* a, const uint32_t* b) {
    asm volatile(
        "mma.sync.aligned.m16n8k8.row.col.f32.tf32.tf32.f32 "
        "{%0,%1,%2,%3}, {%4,%5,%6,%7}, {%8,%9}, {%0,%1,%2,%3};"
        : "+f"(d[0]), "+f"(d[1]), "+f"(d[2]), "+f"(d[3])
        : "r"(a[0]), "r"(a[1]), "r"(a[2]), "r"(a[3]), "r"(b[0]), "r"(b[1]));
}

// ===========================================================================
// Kernel 1: router. 32 tokens per CTA, gate_w cached in SMEM (64 KB dynamic).
// ===========================================================================
#define RT_TOK 32
__global__ __launch_bounds__(256)
void router_kernel(const float* __restrict__ x, const float* __restrict__ gw) {
    extern __shared__ float sgw[];   // [NEXP][HDIM]
    int tid = threadIdx.x;
    int m_base = blockIdx.x * RT_TOK;

    for (int i = tid; i < NEXP * HDIM / 4; i += 256)
        ((float4*)sgw)[i] = ((const float4*)gw)[i];
    __syncthreads();

    int wid = tid >> 5, lane = tid & 31;
    int m0 = m_base + wid * 4;   // 4 tokens per warp

    float acc[4][NEXP];
#pragma unroll
    for (int t = 0; t < 4; t++)
#pragma unroll
        for (int e = 0; e < NEXP; e++) acc[t][e] = 0.f;

#pragma unroll 4
    for (int it = 0; it < HDIM / 128; it++) {
        int k4 = it * 128 + lane * 4;
        float4 xv[4];
#pragma unroll
        for (int t = 0; t < 4; t++)
            xv[t] = *(const float4*)(x + (size_t)(m0 + t) * HDIM + k4);
#pragma unroll
        for (int e = 0; e < NEXP; e++) {
            float4 gv = *(const float4*)&sgw[e * HDIM + k4];
#pragma unroll
            for (int t = 0; t < 4; t++) {
                acc[t][e] = fmaf(xv[t].x, gv.x, acc[t][e]);
                acc[t][e] = fmaf(xv[t].y, gv.y, acc[t][e]);
                acc[t][e] = fmaf(xv[t].z, gv.z, acc[t][e]);
                acc[t][e] = fmaf(xv[t].w, gv.w, acc[t][e]);
            }
        }
    }

#pragma unroll
    for (int off = 16; off; off >>= 1)
#pragma unroll
        for (int t = 0; t < 4; t++)
#pragma unroll
            for (int e = 0; e < NEXP; e++)
                acc[t][e] += __shfl_xor_sync(0xffffffffu, acc[t][e], off);

    if (lane == 0) {
#pragma unroll
        for (int t = 0; t < 4; t++) {
            float* lg = acc[t];
            float mx = lg[0];
#pragma unroll
            for (int e = 1; e < NEXP; e++) mx = fmaxf(mx, lg[e]);
            float ex[NEXP];
#pragma unroll
            for (int e = 0; e < NEXP; e++) ex[e] = expf(lg[e] - mx);
            int i1 = 0;
#pragma unroll
            for (int e = 1; e < NEXP; e++) if (ex[e] > ex[i1]) i1 = e;
            int i2 = (i1 == 0) ? 1 : 0;
#pragma unroll
            for (int e = 0; e < NEXP; e++) {
                if (e == i1) continue;
                if (ex[e] > ex[i2]) i2 = e;
            }
            float s2 = ex[i1] + ex[i2];
            float* cwm = g_cw + (size_t)(m0 + t) * NEXP;
#pragma unroll
            for (int e = 0; e < NEXP; e++) cwm[e] = 0.f;
            cwm[i1] = ex[i1] / s2;
            cwm[i2] = ex[i2] / s2;
        }
    }
}

// ===========================================================================
// Kernel 2: LoRA down-projection t = x @ A^T (SIMT fp32 — small, keep exact)
// ===========================================================================
__global__ __launch_bounds__(256)
void loraA_kernel(const float* __restrict__ x, const float* __restrict__ Aw) {
    __shared__ float As[16][64];
    __shared__ float Bs[16][64];

    int n0 = blockIdx.x * 64;
    int m0 = blockIdx.y * 64;
    int tid = threadIdx.x;
    int tx = tid & 15;
    int ty = tid >> 4;

    float acc[4][4];
#pragma unroll
    for (int i = 0; i < 4; i++)
#pragma unroll
        for (int j = 0; j < 4; j++) acc[i][j] = 0.f;

    int row = tid >> 2;
    int c4 = (tid & 3) * 4;

    for (int k0 = 0; k0 < HDIM; k0 += 16) {
        float4 va = *(const float4*)(x + (size_t)(m0 + row) * HDIM + k0 + c4);
        As[c4 + 0][row] = va.x; As[c4 + 1][row] = va.y;
        As[c4 + 2][row] = va.z; As[c4 + 3][row] = va.w;
        float4 vb = *(const float4*)(Aw + (size_t)(n0 + row) * HDIM + k0 + c4);
        Bs[c4 + 0][row] = vb.x; Bs[c4 + 1][row] = vb.y;
        Bs[c4 + 2][row] = vb.z; Bs[c4 + 3][row] = vb.w;
        __syncthreads();

#pragma unroll
        for (int kk = 0; kk < 16; kk++) {
            float a[4], b[4];
            *(float4*)a = *(const float4*)&As[kk][ty * 4];
            *(float4*)b = *(const float4*)&Bs[kk][tx * 4];
#pragma unroll
            for (int i = 0; i < 4; i++)
#pragma unroll
                for (int j = 0; j < 4; j++)
                    acc[i][j] = fmaf(a[i], b[j], acc[i][j]);
        }
        __syncthreads();
    }

#pragma unroll
    for (int i = 0; i < 4; i++) {
        float4 v = make_float4(acc[i][0], acc[i][1], acc[i][2], acc[i][3]);
        *(float4*)(g_t + (size_t)(m0 + ty * 4 + i) * ER + n0 + tx * 4) = v;
    }
}

// ===========================================================================
// Kernel 3: main GEMM via mma.sync tf32 (compute_103-legal tensor path).
//   out[m,o] = sum_k x[m,k]*W[o,k] + sum_j (alpha*cw[m,e]*t[m,j]) * Bw[e,o,r]
//   CTA tile 128x128, BK=32, double-buffered cp.async. 8 warps: 4(M) x 2(N),
//   warp tile 32x64 -> 2 m16 tiles x 8 n8 tiles of m16n8k8.
// ===========================================================================
#define BM 128
#define BN 128
#define BK 32
#define LDK 36                         // padded row stride (floats): bank=(4*row+k)%32
#define NC_MAIN (HDIM / BK)            // 64
#define NC_TOT  (NC_MAIN + ER / BK)    // 68
#define STAGE_FLOATS ((BM + BN) * LDK) // 9216 floats = 36 KB per stage
#define GEMM_SMEM (2 * STAGE_FLOATS * 4)  // 73728 B

// Stage one K-chunk into smem stage s. Main chunks use cp.async; LoRA chunks
// (c >= NC_MAIN) need a scale multiply so they use plain stores.
__device__ __forceinline__ void load_chunk(
    float* sm, uint32_t sm_addr, int s, int c, int m0, int n0,
    const float* __restrict__ x, const float* __restrict__ w,
    const float* __restrict__ Bw, int tid)
{
    float*   stage   = sm + s * STAGE_FLOATS;
    uint32_t stage_u = sm_addr + s * STAGE_FLOATS * 4;

    if (c < NC_MAIN) {
        int k0 = c * BK;
#pragma unroll
        for (int i = 0; i < 4; i++) {             // A: 128 rows x 8 float4
            int idx = tid + i * 256;
            int row = idx >> 3, q = idx & 7;
            CP_ASYNC16(stage_u + (uint32_t)(row * LDK + q * 4) * 4,
                       x + (size_t)(m0 + row) * HDIM + k0 + q * 4);
        }
#pragma unroll
        for (int i = 0; i < 4; i++) {             // B: 128 rows x 8 float4
            int idx = tid + i * 256;
            int row = idx >> 3, q = idx & 7;
            CP_ASYNC16(stage_u + (uint32_t)(BM * LDK + row * LDK + q * 4) * 4,
                       w + (size_t)(n0 + row) * HDIM + k0 + q * 4);
        }
    } else {
        int j0 = (c - NC_MAIN) * BK;   // LoRA column base (2 experts per chunk)
#pragma unroll
        for (int i = 0; i < 4; i++) {             // A: alpha * cw * t
            int idx = tid + i * 256;
            int row = idx >> 3, q = idx & 7;
            int j = j0 + q * 4;
            int e = j >> 4;
            float scale = ALPHA * g_cw[(size_t)(m0 + row) * NEXP + e];
            float4 v = *(const float4*)(g_t + (size_t)(m0 + row) * ER + j);
            float* d = stage + row * LDK + q * 4;
            d[0] = v.x * scale; d[1] = v.y * scale;
            d[2] = v.z * scale; d[3] = v.w * scale;
        }
#pragma unroll
        for (int i = 0; i < 4; i++) {             // B: Bw[e, n, r] (r contiguous)
            int idx = tid + i * 256;
            int row = idx >> 3, q = idx & 7;
            int j = j0 + q * 4;
            int e = j >> 4, r = j & 15;
            float4 v = *(const float4*)(Bw + (((size_t)e * ODIM + n0 + row) << 4) + r);
            float* d = stage + BM * LDK + row * LDK + q * 4;
            d[0] = v.x; d[1] = v.y; d[2] = v.z; d[3] = v.w;
        }
    }
}

__global__ __launch_bounds__(256, 2)
void gemm_tf32(const float* __restrict__ x, const float* __restrict__ w,
               const float* __restrict__ Bw, float* __restrict__ out) {
    extern __shared__ float sm[];
    uint32_t sm_addr = smem_u32(sm);
    int tid = threadIdx.x;
    int wid = tid >> 5, lane = tid & 31;
    int warp_m = wid & 3;          // 4 warps in M
    int warp_n = wid >> 2;         // 2 warps in N
    int g = lane >> 2, tg = lane & 3;
    int n0 = blockIdx.x * BN;
    int m0 = blockIdx.y * BM;

    float acc[2][8][4];
#pragma unroll
    for (int i = 0; i < 2; i++)
#pragma unroll
        for (int j = 0; j < 8; j++)
#pragma unroll
            for (int q = 0; q < 4; q++) acc[i][j][q] = 0.f;

    // prologue
    load_chunk(sm, sm_addr, 0, 0, m0, n0, x, w, Bw, tid);
    CP_COMMIT();

    for (int c = 0; c < NC_TOT; c++) {
        if (c + 1 < NC_TOT) {
            load_chunk(sm, sm_addr, (c + 1) & 1, c + 1, m0, n0, x, w, Bw, tid);
            CP_COMMIT();
            CP_WAIT(1);
        } else {
            CP_WAIT(0);
        }
        __syncthreads();

        const float* As = sm + (c & 1) * STAGE_FLOATS;
        const float* Bs = As + BM * LDK;

#pragma unroll
        for (int ks = 0; ks < 4; ks++) {
            int k0 = ks * 8;
            uint32_t af[2][4];
#pragma unroll
            for (int i = 0; i < 2; i++) {
                int row = warp_m * 32 + i * 16 + g;
                af[i][0] = f2tf32(As[row * LDK + k0 + tg]);
                af[i][1] = f2tf32(As[(row + 8) * LDK + k0 + tg]);
                af[i][2] = f2tf32(As[row * LDK + k0 + tg + 4]);
                af[i][3] = f2tf32(As[(row + 8) * LDK + k0 + tg + 4]);
            }
            uint32_t bf[8][2];
#pragma unroll
            for (int j = 0; j < 8; j++) {
                int n = warp_n * 64 + j * 8 + g;
                bf[j][0] = f2tf32(Bs[n * LDK + k0 + tg]);
                bf[j][1] = f2tf32(Bs[n * LDK + k0 + tg + 4]);
            }
#pragma unroll
            for (int i = 0; i < 2; i++)
#pragma unroll
                for (int j = 0; j < 8; j++)
                    mma_tf32(acc[i][j], af[i], bf[j]);
        }
        __syncthreads();
    }

    // epilogue: each thread owns cols (2*tg, 2*tg+1), rows g and g+8 per tile
#pragma unroll
    for (int i = 0; i < 2; i++) {
        int m = m0 + warp_m * 32 + i * 16 + g;
#pragma unroll
        for (int j = 0; j < 8; j++) {
            int n = n0 + warp_n * 64 + j * 8 + tg * 2;
            *(float2*)(out + (size_t)m * ODIM + n) =
                make_float2(acc[i][j][0], acc[i][j][1]);
            *(float2*)(out + (size_t)(m + 8) * ODIM + n) =
                make_float2(acc[i][j][2], acc[i][j][3]);
        }
    }
}

// ===========================================================================
extern "C" void kernel_launch(void* const* d_in, const int* in_sizes, int n_in,
                              void* d_out, int out_size) {
    const float* x  = (const float*)d_in[0];   // [2,2048,2048]
    const float* w  = (const float*)d_in[1];   // [2048,2048]
    const float* gw = (const float*)d_in[2];   // [8,2048]
    const float* Aw = (const float*)d_in[3];   // [8,16,2048] -> [128,2048]
    const float* Bw = (const float*)d_in[4];   // [8,2048,16]
    float* out = (float*)d_out;

    cudaFuncSetAttribute(router_kernel, cudaFuncAttributeMaxDynamicSharedMemorySize,
                         NEXP * HDIM * 4);
    cudaFuncSetAttribute(gemm_tf32, cudaFuncAttributeMaxDynamicSharedMemorySize,
                         GEMM_SMEM);

    router_kernel<<<M_TOK / RT_TOK, 256, NEXP * HDIM * 4>>>(x, gw);

    dim3 gA(ER / 64, M_TOK / 64);
    loraA_kernel<<<gA, 256>>>(x, Aw);

    dim3 gM(ODIM / BN, M_TOK / BM);   // (16, 32)
    gemm_tf32<<<gM, 256, GEMM_SMEM>>>(x, w, Bw, out);
}

// round 12
// speedup vs baseline: 3.1550x; 1.2369x over previous
#include <cuda_runtime.h>
#include <cstdint>

// Problem shapes (fixed for this benchmark instance)
#define M_TOK 4096   // B*S
#define HDIM  2048   // H
#define ODIM  2048   // O
#define NEXP  8
#define RANK  16
#define ER    128    // NEXP*RANK
#define ALPHA 16.0f
#define KTOT  (HDIM + ER)   // 2176: fused K (base + LoRA columns)

// Scratch (no cudaMalloc allowed)
__device__ float g_cw[M_TOK * NEXP];       // combine weights
__device__ float g_tp[2][M_TOK * ER];      // loraA split-K partials
__device__ float g_xr[M_TOK * KTOT];       // tf32-rounded, k-permuted [x | a*cw*t]
__device__ float g_wr[ODIM  * KTOT];       // tf32-rounded, k-permuted [W | Bw]

// ===========================================================================
// PTX helpers — ONLY compute_103-legal features (sm_80-era PTX).
// ===========================================================================
__device__ __forceinline__ uint32_t smem_u32(const void* p) {
    uint32_t a;
    asm("{ .reg .u64 t; cvta.to.shared.u64 t, %1; cvt.u32.u64 %0, t; }"
        : "=r"(a) : "l"(p));
    return a;
}

__device__ __forceinline__ float f2tf32f(float x) {
    uint32_t r;
    asm("cvt.rna.tf32.f32 %0, %1;" : "=r"(r) : "f"(x));
    return __uint_as_float(r);
}

#define CP_ASYNC16(dst_u32, src_ptr) \
    asm volatile("cp.async.cg.shared.global [%0], [%1], 16;" \
                 :: "r"(dst_u32), "l"(src_ptr) : "memory")
#define CP_COMMIT() asm volatile("cp.async.commit_group;" ::: "memory")
#define CP_WAIT(n)  asm volatile("cp.async.wait_group %0;" :: "n"(n) : "memory")

// D += A*B, tf32 m16n8k8 (row.col), fp32 accumulate. Operands are raw b32
// bits of floats that are already exactly tf32-representable.
__device__ __forceinline__ void mma_tf32(float* d, const uint32_t* a, const uint32_t* b) {
    asm volatile(
        "mma.sync.aligned.m16n8k8.row.col.f32.tf32.tf32.f32 "
        "{%0,%1,%2,%3}, {%4,%5,%6,%7}, {%8,%9}, {%0,%1,%2,%3};"
        : "+f"(d[0]), "+f"(d[1]), "+f"(d[2]), "+f"(d[3])
        : "r"(a[0]), "r"(a[1]), "r"(a[2]), "r"(a[3]), "r"(b[0]), "r"(b[1]));
}

// Round 8 consecutive floats to tf32 and store k-permuted [k0,k4,k1,k5,k2,k6,k3,k7]
__device__ __forceinline__ void round_perm8(const float* __restrict__ src,
                                            float* __restrict__ dst, float scale) {
    float4 a = *(const float4*)src;
    float4 b = *(const float4*)(src + 4);
    float4 o0 = make_float4(f2tf32f(a.x * scale), f2tf32f(b.x * scale),
                            f2tf32f(a.y * scale), f2tf32f(b.y * scale));
    float4 o1 = make_float4(f2tf32f(a.z * scale), f2tf32f(b.z * scale),
                            f2tf32f(a.w * scale), f2tf32f(b.w * scale));
    *(float4*)dst = o0;
    *(float4*)(dst + 4) = o1;
}

// ===========================================================================
// prep_x: g_xr[m][0:2048] = round+perm(x[m])
// ===========================================================================
__global__ __launch_bounds__(256)
void prep_x(const float* __restrict__ x) {
    int m = blockIdx.x;
    int b = threadIdx.x;                 // 256 blocks of 8 per row
    round_perm8(x + (size_t)m * HDIM + b * 8,
                g_xr + (size_t)m * KTOT + b * 8, 1.0f);
}

// ===========================================================================
// prep_w: g_wr[n][0:2048] = round+perm(W[n]); g_wr[n][2048+j] = round+perm(Bw)
// ===========================================================================
__global__ __launch_bounds__(256)
void prep_w(const float* __restrict__ w, const float* __restrict__ Bw) {
    int n = blockIdx.x;
    for (int b = threadIdx.x; b < KTOT / 8; b += 256) {
        int k = b * 8;
        const float* src;
        if (k < HDIM) {
            src = w + (size_t)n * HDIM + k;
        } else {
            int j = k - HDIM;            // 8-block lies within one expert (16 | e-span)
            int e = j >> 4, r = j & 15;
            src = Bw + (((size_t)e * ODIM + n) << 4) + r;
        }
        round_perm8(src, g_wr + (size_t)n * KTOT + k, 1.0f);
    }
}

// ===========================================================================
// prep_xt: g_xr[m][2048+j] = round+perm(alpha * cw[m,e] * (tp0+tp1)[m,j])
// ===========================================================================
__global__ __launch_bounds__(256)
void prep_xt() {
    int tid = threadIdx.x;
    int m = blockIdx.x * 16 + (tid >> 4);
    int j = (tid & 15) * 8;              // 8-block within one expert
    int e = j >> 4;
    float scale = ALPHA * g_cw[(size_t)m * NEXP + e];
    float buf[8];
    const float* t0 = g_tp[0] + (size_t)m * ER + j;
    const float* t1 = g_tp[1] + (size_t)m * ER + j;
#pragma unroll
    for (int q = 0; q < 8; q++) buf[q] = t0[q] + t1[q];
    round_perm8(buf, g_xr + (size_t)m * KTOT + HDIM + j, scale);
}

// ===========================================================================
// Kernel: router. 16 tokens per CTA (grid 256), gate_w cached in SMEM.
// ===========================================================================
#define RT_TOK 16
__global__ __launch_bounds__(256)
void router_kernel(const float* __restrict__ x, const float* __restrict__ gw) {
    extern __shared__ float sgw[];   // [NEXP][HDIM] = 64 KB
    int tid = threadIdx.x;
    int m_base = blockIdx.x * RT_TOK;

    for (int i = tid; i < NEXP * HDIM / 4; i += 256)
        ((float4*)sgw)[i] = ((const float4*)gw)[i];
    __syncthreads();

    int wid = tid >> 5, lane = tid & 31;
    int m0 = m_base + wid * 2;   // 2 tokens per warp

    float acc[2][NEXP];
#pragma unroll
    for (int t = 0; t < 2; t++)
#pragma unroll
        for (int e = 0; e < NEXP; e++) acc[t][e] = 0.f;

#pragma unroll 4
    for (int it = 0; it < HDIM / 128; it++) {
        int k4 = it * 128 + lane * 4;
        float4 xv[2];
#pragma unroll
        for (int t = 0; t < 2; t++)
            xv[t] = *(const float4*)(x + (size_t)(m0 + t) * HDIM + k4);
#pragma unroll
        for (int e = 0; e < NEXP; e++) {
            float4 gv = *(const float4*)&sgw[e * HDIM + k4];
#pragma unroll
            for (int t = 0; t < 2; t++) {
                acc[t][e] = fmaf(xv[t].x, gv.x, acc[t][e]);
                acc[t][e] = fmaf(xv[t].y, gv.y, acc[t][e]);
                acc[t][e] = fmaf(xv[t].z, gv.z, acc[t][e]);
                acc[t][e] = fmaf(xv[t].w, gv.w, acc[t][e]);
            }
        }
    }

#pragma unroll
    for (int off = 16; off; off >>= 1)
#pragma unroll
        for (int t = 0; t < 2; t++)
#pragma unroll
            for (int e = 0; e < NEXP; e++)
                acc[t][e] += __shfl_xor_sync(0xffffffffu, acc[t][e], off);

    if (lane == 0) {
#pragma unroll
        for (int t = 0; t < 2; t++) {
            float* lg = acc[t];
            float mx = lg[0];
#pragma unroll
            for (int e = 1; e < NEXP; e++) mx = fmaxf(mx, lg[e]);
            float ex[NEXP];
#pragma unroll
            for (int e = 0; e < NEXP; e++) ex[e] = expf(lg[e] - mx);
            int i1 = 0;
#pragma unroll
            for (int e = 1; e < NEXP; e++) if (ex[e] > ex[i1]) i1 = e;
            int i2 = (i1 == 0) ? 1 : 0;
#pragma unroll
            for (int e = 0; e < NEXP; e++) {
                if (e == i1) continue;
                if (ex[e] > ex[i2]) i2 = e;
            }
            float s2 = ex[i1] + ex[i2];
            float* cwm = g_cw + (size_t)(m0 + t) * NEXP;
#pragma unroll
            for (int e = 0; e < NEXP; e++) cwm[e] = 0.f;
            cwm[i1] = ex[i1] / s2;
            cwm[i2] = ex[i2] / s2;
        }
    }
}

// ===========================================================================
// Kernel: LoRA down-projection, split-K=2. tp[seg] = x[:, seg] @ A[:, seg]^T
// ===========================================================================
__global__ __launch_bounds__(256)
void loraA_kernel(const float* __restrict__ x, const float* __restrict__ Aw) {
    __shared__ float As[16][64];
    __shared__ float Bs[16][64];

    int n0 = blockIdx.x * 64;
    int m0 = blockIdx.y * 64;
    int seg = blockIdx.z;
    int tid = threadIdx.x;
    int tx = tid & 15;
    int ty = tid >> 4;

    float acc[4][4];
#pragma unroll
    for (int i = 0; i < 4; i++)
#pragma unroll
        for (int j = 0; j < 4; j++) acc[i][j] = 0.f;

    int row = tid >> 2;
    int c4 = (tid & 3) * 4;
    int kbeg = seg * (HDIM / 2), kend = kbeg + HDIM / 2;

    for (int k0 = kbeg; k0 < kend; k0 += 16) {
        float4 va = *(const float4*)(x + (size_t)(m0 + row) * HDIM + k0 + c4);
        As[c4 + 0][row] = va.x; As[c4 + 1][row] = va.y;
        As[c4 + 2][row] = va.z; As[c4 + 3][row] = va.w;
        float4 vb = *(const float4*)(Aw + (size_t)(n0 + row) * HDIM + k0 + c4);
        Bs[c4 + 0][row] = vb.x; Bs[c4 + 1][row] = vb.y;
        Bs[c4 + 2][row] = vb.z; Bs[c4 + 3][row] = vb.w;
        __syncthreads();

#pragma unroll
        for (int kk = 0; kk < 16; kk++) {
            float a[4], b[4];
            *(float4*)a = *(const float4*)&As[kk][ty * 4];
            *(float4*)b = *(const float4*)&Bs[kk][tx * 4];
#pragma unroll
            for (int i = 0; i < 4; i++)
#pragma unroll
                for (int j = 0; j < 4; j++)
                    acc[i][j] = fmaf(a[i], b[j], acc[i][j]);
        }
        __syncthreads();
    }

    float* dst = g_tp[seg];
#pragma unroll
    for (int i = 0; i < 4; i++) {
        float4 v = make_float4(acc[i][0], acc[i][1], acc[i][2], acc[i][3]);
        *(float4*)(dst + (size_t)(m0 + ty * 4 + i) * ER + n0 + tx * 4) = v;
    }
}

// ===========================================================================
// Main GEMM: out = g_xr @ g_wr^T over K=2176. Pure tf32 mma.sync.
//   CTA 128x128, 4 warps (2x2), warp tile 64x64, BK=32, LDK=40 (pad),
//   double-buffered cp.async. Data pre-rounded+permuted -> no cvt, LDS.64 frags.
// ===========================================================================
#define BM 128
#define BN 128
#define BK 32
#define LDK 40
#define NCH (KTOT / BK)                  // 68
#define STG_FLTS ((BM + BN) * LDK)       // 10240 floats = 40 KB / stage
#define GEMM_SMEM (2 * STG_FLTS * 4)     // 81920 B

__device__ __forceinline__ void load_chunk(uint32_t sm_addr, int s, int c,
                                           int m0, int n0, int tid) {
    uint32_t stage_u = sm_addr + s * STG_FLTS * 4;
    int k0 = c * BK;
#pragma unroll
    for (int i = 0; i < 8; i++) {        // A: 128 rows x 8 float4
        int idx = tid + i * 128;
        int row = idx >> 3, q = idx & 7;
        CP_ASYNC16(stage_u + (uint32_t)(row * LDK + q * 4) * 4,
                   g_xr + (size_t)(m0 + row) * KTOT + k0 + q * 4);
    }
#pragma unroll
    for (int i = 0; i < 8; i++) {        // B: 128 rows x 8 float4
        int idx = tid + i * 128;
        int row = idx >> 3, q = idx & 7;
        CP_ASYNC16(stage_u + (uint32_t)(BM * LDK + row * LDK + q * 4) * 4,
                   g_wr + (size_t)(n0 + row) * KTOT + k0 + q * 4);
    }
}

__global__ __launch_bounds__(128, 2)
void gemm_tf32(float* __restrict__ out) {
    extern __shared__ float sm[];
    uint32_t sm_addr = smem_u32(sm);
    int tid = threadIdx.x;
    int wid = tid >> 5, lane = tid & 31;
    int wm = wid & 1;                    // 2 warps in M
    int wn = wid >> 1;                   // 2 warps in N
    int g = lane >> 2, tg = lane & 3;
    int n0 = blockIdx.x * BN;
    int m0 = blockIdx.y * BM;

    float acc[4][8][4];
#pragma unroll
    for (int i = 0; i < 4; i++)
#pragma unroll
        for (int j = 0; j < 8; j++)
#pragma unroll
            for (int q = 0; q < 4; q++) acc[i][j][q] = 0.f;

    load_chunk(sm_addr, 0, 0, m0, n0, tid);
    CP_COMMIT();

    for (int c = 0; c < NCH; c++) {
        if (c + 1 < NCH) {
            load_chunk(sm_addr, (c + 1) & 1, c + 1, m0, n0, tid);
            CP_COMMIT();
            CP_WAIT(1);
        } else {
            CP_WAIT(0);
        }
        __syncthreads();

        const float* As = sm + (c & 1) * STG_FLTS;
        const float* Bs = As + BM * LDK;

#pragma unroll
        for (int ks = 0; ks < 4; ks++) {
            int kb = ks * 8 + 2 * tg;    // permuted: float2 = (k=tg, k=tg+4)
            uint32_t af[4][4];
#pragma unroll
            for (int i = 0; i < 4; i++) {
                int row = wm * 64 + i * 16 + g;
                float2 lo = *(const float2*)&As[row * LDK + kb];
                float2 hi = *(const float2*)&As[(row + 8) * LDK + kb];
                af[i][0] = __float_as_uint(lo.x);
                af[i][1] = __float_as_uint(hi.x);
                af[i][2] = __float_as_uint(lo.y);
                af[i][3] = __float_as_uint(hi.y);
            }
            uint32_t bf[8][2];
#pragma unroll
            for (int j = 0; j < 8; j++) {
                int n = wn * 64 + j * 8 + g;
                float2 v = *(const float2*)&Bs[n * LDK + kb];
                bf[j][0] = __float_as_uint(v.x);
                bf[j][1] = __float_as_uint(v.y);
            }
#pragma unroll
            for (int i = 0; i < 4; i++)
#pragma unroll
                for (int j = 0; j < 8; j++)
                    mma_tf32(acc[i][j], af[i], bf[j]);
        }
        __syncthreads();
    }

    // epilogue
#pragma unroll
    for (int i = 0; i < 4; i++) {
        int m = m0 + wm * 64 + i * 16 + g;
#pragma unroll
        for (int j = 0; j < 8; j++) {
            int n = n0 + wn * 64 + j * 8 + tg * 2;
            *(float2*)(out + (size_t)m * ODIM + n) =
                make_float2(acc[i][j][0], acc[i][j][1]);
            *(float2*)(out + (size_t)(m + 8) * ODIM + n) =
                make_float2(acc[i][j][2], acc[i][j][3]);
        }
    }
}

// ===========================================================================
extern "C" void kernel_launch(void* const* d_in, const int* in_sizes, int n_in,
                              void* d_out, int out_size) {
    const float* x  = (const float*)d_in[0];   // [2,2048,2048]
    const float* w  = (const float*)d_in[1];   // [2048,2048]
    const float* gw = (const float*)d_in[2];   // [8,2048]
    const float* Aw = (const float*)d_in[3];   // [8,16,2048] -> [128,2048]
    const float* Bw = (const float*)d_in[4];   // [8,2048,16]
    float* out = (float*)d_out;

    cudaFuncSetAttribute(router_kernel, cudaFuncAttributeMaxDynamicSharedMemorySize,
                         NEXP * HDIM * 4);
    cudaFuncSetAttribute(gemm_tf32, cudaFuncAttributeMaxDynamicSharedMemorySize,
                         GEMM_SMEM);

    prep_x<<<M_TOK, 256>>>(x);
    prep_w<<<ODIM, 256>>>(w, Bw);

    router_kernel<<<M_TOK / RT_TOK, 256, NEXP * HDIM * 4>>>(x, gw);

    dim3 gA(ER / 64, M_TOK / 64, 2);           // split-K = 2
    loraA_kernel<<<gA, 256>>>(x, Aw);

    prep_xt<<<M_TOK / 16, 256>>>();

    dim3 gM(ODIM / BN, M_TOK / BM);            // (16, 32)
    gemm_tf32<<<gM, 128, GEMM_SMEM>>>(out);
}

// round 14
// speedup vs baseline: 3.1676x; 1.0040x over previous
#include <cuda_runtime.h>
#include <cstdint>

// Problem shapes (fixed for this benchmark instance)
#define M_TOK 4096   // B*S
#define HDIM  2048   // H
#define ODIM  2048   // O
#define NEXP  8
#define RANK  16
#define ER    128    // NEXP*RANK
#define ALPHA 16.0f
#define KTOT  (HDIM + ER)   // 2176: fused K (base + LoRA columns)

// Scratch (no cudaMalloc allowed)
__device__ float g_cw[M_TOK * NEXP];       // combine weights
__device__ float g_tp[2][M_TOK * ER];      // loraA split-K partials
__device__ float g_xr[M_TOK * KTOT];       // tf32-rounded, k-permuted [x | a*cw*t]
__device__ float g_wr[ODIM  * KTOT];       // tf32-rounded, k-permuted [W | Bw]

// ===========================================================================
// PTX helpers — ONLY compute_103-legal features (sm_80-era PTX).
// ===========================================================================
__device__ __forceinline__ uint32_t smem_u32(const void* p) {
    uint32_t a;
    asm("{ .reg .u64 t; cvta.to.shared.u64 t, %1; cvt.u32.u64 %0, t; }"
        : "=r"(a) : "l"(p));
    return a;
}

__device__ __forceinline__ float f2tf32f(float x) {
    uint32_t r;
    asm("cvt.rna.tf32.f32 %0, %1;" : "=r"(r) : "f"(x));
    return __uint_as_float(r);
}

#define CP_ASYNC16(dst_u32, src_ptr) \
    asm volatile("cp.async.cg.shared.global [%0], [%1], 16;" \
                 :: "r"(dst_u32), "l"(src_ptr) : "memory")
#define CP_COMMIT() asm volatile("cp.async.commit_group;" ::: "memory")
#define CP_WAIT(n)  asm volatile("cp.async.wait_group %0;" :: "n"(n) : "memory")

// D += A*B, tf32 m16n8k8 (row.col), fp32 accumulate. Operands are raw b32
// bits of floats that are already exactly tf32-representable.
__device__ __forceinline__ void mma_tf32(float* d, const uint32_t* a, const uint32_t* b) {
    asm volatile(
        "mma.sync.aligned.m16n8k8.row.col.f32.tf32.tf32.f32 "
        "{%0,%1,%2,%3}, {%4,%5,%6,%7}, {%8,%9}, {%0,%1,%2,%3};"
        : "+f"(d[0]), "+f"(d[1]), "+f"(d[2]), "+f"(d[3])
        : "r"(a[0]), "r"(a[1]), "r"(a[2]), "r"(a[3]), "r"(b[0]), "r"(b[1]));
}

// Round 8 consecutive floats to tf32 and store k-permuted [k0,k4,k1,k5,k2,k6,k3,k7]
__device__ __forceinline__ void round_perm8(const float* __restrict__ src,
                                            float* __restrict__ dst, float scale) {
    float4 a = *(const float4*)src;
    float4 b = *(const float4*)(src + 4);
    float4 o0 = make_float4(f2tf32f(a.x * scale), f2tf32f(b.x * scale),
                            f2tf32f(a.y * scale), f2tf32f(b.y * scale));
    float4 o1 = make_float4(f2tf32f(a.z * scale), f2tf32f(b.z * scale),
                            f2tf32f(a.w * scale), f2tf32f(b.w * scale));
    *(float4*)dst = o0;
    *(float4*)(dst + 4) = o1;
}

// ===========================================================================
// prep_x: g_xr[m][0:2048] = round+perm(x[m])
// ===========================================================================
__global__ __launch_bounds__(256)
void prep_x(const float* __restrict__ x) {
    int m = blockIdx.x;
    int b = threadIdx.x;                 // 256 blocks of 8 per row
    round_perm8(x + (size_t)m * HDIM + b * 8,
                g_xr + (size_t)m * KTOT + b * 8, 1.0f);
}

// ===========================================================================
// prep_w: g_wr[n][0:2048] = round+perm(W[n]); g_wr[n][2048+j] = round+perm(Bw)
// ===========================================================================
__global__ __launch_bounds__(256)
void prep_w(const float* __restrict__ w, const float* __restrict__ Bw) {
    int n = blockIdx.x;
    for (int b = threadIdx.x; b < KTOT / 8; b += 256) {
        int k = b * 8;
        const float* src;
        if (k < HDIM) {
            src = w + (size_t)n * HDIM + k;
        } else {
            int j = k - HDIM;            // 8-block lies within one expert (16 | e-span)
            int e = j >> 4, r = j & 15;
            src = Bw + (((size_t)e * ODIM + n) << 4) + r;
        }
        round_perm8(src, g_wr + (size_t)n * KTOT + k, 1.0f);
    }
}

// ===========================================================================
// prep_xt: g_xr[m][2048+j] = round+perm(alpha * cw[m,e] * (tp0+tp1)[m,j])
// ===========================================================================
__global__ __launch_bounds__(256)
void prep_xt() {
    int tid = threadIdx.x;
    int m = blockIdx.x * 16 + (tid >> 4);
    int j = (tid & 15) * 8;              // 8-block within one expert
    int e = j >> 4;
    float scale = ALPHA * g_cw[(size_t)m * NEXP + e];
    float buf[8];
    const float* t0 = g_tp[0] + (size_t)m * ER + j;
    const float* t1 = g_tp[1] + (size_t)m * ER + j;
#pragma unroll
    for (int q = 0; q < 8; q++) buf[q] = t0[q] + t1[q];
    round_perm8(buf, g_xr + (size_t)m * KTOT + HDIM + j, scale);
}

// ===========================================================================
// Kernel: router. 16 tokens per CTA (grid 256), gate_w cached in SMEM.
// ===========================================================================
#define RT_TOK 16
__global__ __launch_bounds__(256)
void router_kernel(const float* __restrict__ x, const float* __restrict__ gw) {
    extern __shared__ float sgw[];   // [NEXP][HDIM] = 64 KB
    int tid = threadIdx.x;
    int m_base = blockIdx.x * RT_TOK;

    for (int i = tid; i < NEXP * HDIM / 4; i += 256)
        ((float4*)sgw)[i] = ((const float4*)gw)[i];
    __syncthreads();

    int wid = tid >> 5, lane = tid & 31;
    int m0 = m_base + wid * 2;   // 2 tokens per warp

    float acc[2][NEXP];
#pragma unroll
    for (int t = 0; t < 2; t++)
#pragma unroll
        for (int e = 0; e < NEXP; e++) acc[t][e] = 0.f;

#pragma unroll 4
    for (int it = 0; it < HDIM / 128; it++) {
        int k4 = it * 128 + lane * 4;
        float4 xv[2];
#pragma unroll
        for (int t = 0; t < 2; t++)
            xv[t] = *(const float4*)(x + (size_t)(m0 + t) * HDIM + k4);
#pragma unroll
        for (int e = 0; e < NEXP; e++) {
            float4 gv = *(const float4*)&sgw[e * HDIM + k4];
#pragma unroll
            for (int t = 0; t < 2; t++) {
                acc[t][e] = fmaf(xv[t].x, gv.x, acc[t][e]);
                acc[t][e] = fmaf(xv[t].y, gv.y, acc[t][e]);
                acc[t][e] = fmaf(xv[t].z, gv.z, acc[t][e]);
                acc[t][e] = fmaf(xv[t].w, gv.w, acc[t][e]);
            }
        }
    }

#pragma unroll
    for (int off = 16; off; off >>= 1)
#pragma unroll
        for (int t = 0; t < 2; t++)
#pragma unroll
            for (int e = 0; e < NEXP; e++)
                acc[t][e] += __shfl_xor_sync(0xffffffffu, acc[t][e], off);

    if (lane == 0) {
#pragma unroll
        for (int t = 0; t < 2; t++) {
            float* lg = acc[t];
            float mx = lg[0];
#pragma unroll
            for (int e = 1; e < NEXP; e++) mx = fmaxf(mx, lg[e]);
            float ex[NEXP];
#pragma unroll
            for (int e = 0; e < NEXP; e++) ex[e] = expf(lg[e] - mx);
            int i1 = 0;
#pragma unroll
            for (int e = 1; e < NEXP; e++) if (ex[e] > ex[i1]) i1 = e;
            int i2 = (i1 == 0) ? 1 : 0;
#pragma unroll
            for (int e = 0; e < NEXP; e++) {
                if (e == i1) continue;
                if (ex[e] > ex[i2]) i2 = e;
            }
            float s2 = ex[i1] + ex[i2];
            float* cwm = g_cw + (size_t)(m0 + t) * NEXP;
#pragma unroll
            for (int e = 0; e < NEXP; e++) cwm[e] = 0.f;
            cwm[i1] = ex[i1] / s2;
            cwm[i2] = ex[i2] / s2;
        }
    }
}

// ===========================================================================
// Kernel: LoRA down-projection, split-K=2. tp[seg] = x[:, seg] @ A[:, seg]^T
// ===========================================================================
__global__ __launch_bounds__(256)
void loraA_kernel(const float* __restrict__ x, const float* __restrict__ Aw) {
    __shared__ float As[16][64];
    __shared__ float Bs[16][64];

    int n0 = blockIdx.x * 64;
    int m0 = blockIdx.y * 64;
    int seg = blockIdx.z;
    int tid = threadIdx.x;
    int tx = tid & 15;
    int ty = tid >> 4;

    float acc[4][4];
#pragma unroll
    for (int i = 0; i < 4; i++)
#pragma unroll
        for (int j = 0; j < 4; j++) acc[i][j] = 0.f;

    int row = tid >> 2;
    int c4 = (tid & 3) * 4;
    int kbeg = seg * (HDIM / 2), kend = kbeg + HDIM / 2;

    for (int k0 = kbeg; k0 < kend; k0 += 16) {
        float4 va = *(const float4*)(x + (size_t)(m0 + row) * HDIM + k0 + c4);
        As[c4 + 0][row] = va.x; As[c4 + 1][row] = va.y;
        As[c4 + 2][row] = va.z; As[c4 + 3][row] = va.w;
        float4 vb = *(const float4*)(Aw + (size_t)(n0 + row) * HDIM + k0 + c4);
        Bs[c4 + 0][row] = vb.x; Bs[c4 + 1][row] = vb.y;
        Bs[c4 + 2][row] = vb.z; Bs[c4 + 3][row] = vb.w;
        __syncthreads();

#pragma unroll
        for (int kk = 0; kk < 16; kk++) {
            float a[4], b[4];
            *(float4*)a = *(const float4*)&As[kk][ty * 4];
            *(float4*)b = *(const float4*)&Bs[kk][tx * 4];
#pragma unroll
            for (int i = 0; i < 4; i++)
#pragma unroll
                for (int j = 0; j < 4; j++)
                    acc[i][j] = fmaf(a[i], b[j], acc[i][j]);
        }
        __syncthreads();
    }

    float* dst = g_tp[seg];
#pragma unroll
    for (int i = 0; i < 4; i++) {
        float4 v = make_float4(acc[i][0], acc[i][1], acc[i][2], acc[i][3]);
        *(float4*)(dst + (size_t)(m0 + ty * 4 + i) * ER + n0 + tx * 4) = v;
    }
}

// ===========================================================================
// Main GEMM: out = g_xr @ g_wr^T over K=2176. Pure tf32 mma.sync.
//   CTA 128x128, 4 warps (2x2), warp tile 64x64, BK=32, LDK=40 (pad),
//   double-buffered cp.async. Data pre-rounded+permuted -> no cvt, LDS.64 frags.
// ===========================================================================
#define BM 128
#define BN 128
#define BK 32
#define LDK 40
#define NCH (KTOT / BK)                  // 68
#define STG_FLTS ((BM + BN) * LDK)       // 10240 floats = 40 KB / stage
#define GEMM_SMEM (2 * STG_FLTS * 4)     // 81920 B

__device__ __forceinline__ void load_chunk(uint32_t sm_addr, int s, int c,
                                           int m0, int n0, int tid) {
    uint32_t stage_u = sm_addr + s * STG_FLTS * 4;
    int k0 = c * BK;
#pragma unroll
    for (int i = 0; i < 8; i++) {        // A: 128 rows x 8 float4
        int idx = tid + i * 128;
        int row = idx >> 3, q = idx & 7;
        CP_ASYNC16(stage_u + (uint32_t)(row * LDK + q * 4) * 4,
                   g_xr + (size_t)(m0 + row) * KTOT + k0 + q * 4);
    }
#pragma unroll
    for (int i = 0; i < 8; i++) {        // B: 128 rows x 8 float4
        int idx = tid + i * 128;
        int row = idx >> 3, q = idx & 7;
        CP_ASYNC16(stage_u + (uint32_t)(BM * LDK + row * LDK + q * 4) * 4,
                   g_wr + (size_t)(n0 + row) * KTOT + k0 + q * 4);
    }
}

__global__ __launch_bounds__(128, 2)
void gemm_tf32(float* __restrict__ out) {
    extern __shared__ float sm[];
    uint32_t sm_addr = smem_u32(sm);
    int tid = threadIdx.x;
    int wid = tid >> 5, lane = tid & 31;
    int wm = wid & 1;                    // 2 warps in M
    int wn = wid >> 1;                   // 2 warps in N
    int g = lane >> 2, tg = lane & 3;
    int n0 = blockIdx.x * BN;
    int m0 = blockIdx.y * BM;

    float acc[4][8][4];
#pragma unroll
    for (int i = 0; i < 4; i++)
#pragma unroll
        for (int j = 0; j < 8; j++)
#pragma unroll
            for (int q = 0; q < 4; q++) acc[i][j][q] = 0.f;

    load_chunk(sm_addr, 0, 0, m0, n0, tid);
    CP_COMMIT();

    for (int c = 0; c < NCH; c++) {
        if (c + 1 < NCH) {
            load_chunk(sm_addr, (c + 1) & 1, c + 1, m0, n0, tid);
            CP_COMMIT();
            CP_WAIT(1);
        } else {
            CP_WAIT(0);
        }
        __syncthreads();

        const float* As = sm + (c & 1) * STG_FLTS;
        const float* Bs = As + BM * LDK;

#pragma unroll
        for (int ks = 0; ks < 4; ks++) {
            int kb = ks * 8 + 2 * tg;    // permuted: float2 = (k=tg, k=tg+4)
            uint32_t af[4][4];
#pragma unroll
            for (int i = 0; i < 4; i++) {
                int row = wm * 64 + i * 16 + g;
                float2 lo = *(const float2*)&As[row * LDK + kb];
                float2 hi = *(const float2*)&As[(row + 8) * LDK + kb];
                af[i][0] = __float_as_uint(lo.x);
                af[i][1] = __float_as_uint(hi.x);
                af[i][2] = __float_as_uint(lo.y);
                af[i][3] = __float_as_uint(hi.y);
            }
            uint32_t bf[8][2];
#pragma unroll
            for (int j = 0; j < 8; j++) {
                int n = wn * 64 + j * 8 + g;
                float2 v = *(const float2*)&Bs[n * LDK + kb];
                bf[j][0] = __float_as_uint(v.x);
                bf[j][1] = __float_as_uint(v.y);
            }
#pragma unroll
            for (int i = 0; i < 4; i++)
#pragma unroll
                for (int j = 0; j < 8; j++)
                    mma_tf32(acc[i][j], af[i], bf[j]);
        }
        __syncthreads();
    }

    // epilogue
#pragma unroll
    for (int i = 0; i < 4; i++) {
        int m = m0 + wm * 64 + i * 16 + g;
#pragma unroll
        for (int j = 0; j < 8; j++) {
            int n = n0 + wn * 64 + j * 8 + tg * 2;
            *(float2*)(out + (size_t)m * ODIM + n) =
                make_float2(acc[i][j][0], acc[i][j][1]);
            *(float2*)(out + (size_t)(m + 8) * ODIM + n) =
                make_float2(acc[i][j][2], acc[i][j][3]);
        }
    }
}

// ===========================================================================
extern "C" void kernel_launch(void* const* d_in, const int* in_sizes, int n_in,
                              void* d_out, int out_size) {
    const float* x  = (const float*)d_in[0];   // [2,2048,2048]
    const float* w  = (const float*)d_in[1];   // [2048,2048]
    const float* gw = (const float*)d_in[2];   // [8,2048]
    const float* Aw = (const float*)d_in[3];   // [8,16,2048] -> [128,2048]
    const float* Bw = (const float*)d_in[4];   // [8,2048,16]
    float* out = (float*)d_out;

    cudaFuncSetAttribute(router_kernel, cudaFuncAttributeMaxDynamicSharedMemorySize,
                         NEXP * HDIM * 4);
    cudaFuncSetAttribute(gemm_tf32, cudaFuncAttributeMaxDynamicSharedMemorySize,
                         GEMM_SMEM);

    prep_x<<<M_TOK, 256>>>(x);
    prep_w<<<ODIM, 256>>>(w, Bw);

    router_kernel<<<M_TOK / RT_TOK, 256, NEXP * HDIM * 4>>>(x, gw);

    dim3 gA(ER / 64, M_TOK / 64, 2);           // split-K = 2
    loraA_kernel<<<gA, 256>>>(x, Aw);

    prep_xt<<<M_TOK / 16, 256>>>();

    dim3 gM(ODIM / BN, M_TOK / BM);            // (16, 32)
    gemm_tf32<<<gM, 128, GEMM_SMEM>>>(out);
}